// round 13
// baseline (speedup 1.0000x reference)
#include <cuda_runtime.h>
#include <cuda_fp16.h>
#include <cstdint>

// Problem constants
#define Bsz 32
#define Ssz 512
#define Lsz 8
#define Hsz 1024
#define Dsz 64

typedef uint32_t u32;

// Scratch
__device__ float g_E[Bsz * Ssz];
__device__ float g_V[Bsz * Ssz];
// W' = diag(tw) @ W1, fp16, [chunk][d][k] in the exact swizzled smem image (16 x 8 KB)
__device__ __align__(16) char g_Wp[16 * 8192];

// ---------------- PTX wrappers (base ISA, sm_80+) ----------------
__device__ __forceinline__ u32 smem_u32(const void* p) {
    u32 a;
    asm("{ .reg .u64 t; cvta.to.shared.u64 t, %1; cvt.u32.u64 %0, t; }" : "=r"(a) : "l"(p));
    return a;
}
__device__ __forceinline__ void ldsm4(u32* r, u32 addr) {
    asm volatile("ldmatrix.sync.aligned.m8n8.x4.shared.b16 {%0,%1,%2,%3}, [%4];"
                 : "=r"(r[0]), "=r"(r[1]), "=r"(r[2]), "=r"(r[3]) : "r"(addr));
}
__device__ __forceinline__ void mma_fp16(float* c, const u32* a, u32 b0, u32 b1) {
    asm volatile("mma.sync.aligned.m16n8k16.row.col.f32.f16.f16.f32 "
                 "{%0,%1,%2,%3}, {%4,%5,%6,%7}, {%8,%9}, {%0,%1,%2,%3};"
                 : "+f"(c[0]), "+f"(c[1]), "+f"(c[2]), "+f"(c[3])
                 : "r"(a[0]), "r"(a[1]), "r"(a[2]), "r"(a[3]), "r"(b0), "r"(b1));
}
__device__ __forceinline__ u32 pack_h2(float a, float b) {
    __half2 h = __floats2half2_rn(a, b);
    return *reinterpret_cast<u32*>(&h);
}
__device__ __forceinline__ void cp_async16(u32 dst, const void* src) {
    asm volatile("cp.async.cg.shared.global [%0], [%1], 16;" :: "r"(dst), "l"(src));
}
#define CP_COMMIT() asm volatile("cp.async.commit_group;" ::: "memory")
#define CP_WAIT0()  asm volatile("cp.async.wait_group 0;" ::: "memory")

// ---------------- Kernel 0: W' = tw * W1 -> fp16, pre-swizzled ----------------
__global__ __launch_bounds__(256) void prep_wp(
    const float* __restrict__ tw, const float* __restrict__ W1)
{
    int u = blockIdx.x * 256 + threadIdx.x;   // 0..8191
    int d = u & 63;
    int g = u >> 6;                           // k-octet 0..127
    int k0 = g * 8;
    u32 p[4];
    #pragma unroll
    for (int j = 0; j < 4; j++) {
        float wa = W1[(size_t)(k0 + 2 * j) * Dsz + d]     * tw[k0 + 2 * j];
        float wb = W1[(size_t)(k0 + 2 * j + 1) * Dsz + d] * tw[k0 + 2 * j + 1];
        p[j] = pack_h2(wa, wb);
    }
    int c = g >> 3;
    u32 seg = (u32)(g & 7);
    u32 off = (u32)(c * 8192) + (u32)(d << 7) + ((seg << 4) ^ ((u32)(d & 7) << 4));
    *(uint4*)(g_Wp + off) = make_uint4(p[0], p[1], p[2], p[3]);
}

// ---------------- Kernel 1: token MLP, X fully resident in smem ----------------
#define TMB 16                // tokens per block
#define KCH 64                // K per chunk
#define NCHUNK (Hsz / KCH)    // 16
#define X_OFF 0               // X: 16 chunks x (16 rows x 128B) = 32 KB
#define W_OFF 32768           // W: 2 buffers x 8 KB
#define EP_OFF (W_OFF + 2 * 8192)     // 49152
#define SMEM_TOTAL (EP_OFF + 4 * TMB * 4)   // 49408

__global__ __launch_bounds__(128, 4) void token_mlp_mma(
    const float* __restrict__ hidden,
    const float* __restrict__ b1,
    const float* __restrict__ W2,
    const float* __restrict__ b2,
    const float* __restrict__ Ws)
{
    extern __shared__ char smem[];
    const u32 sb = smem_u32(smem);
    float* Epart = (float*)(smem + EP_OFF);

    const int tid  = threadIdx.x;
    const int w    = tid >> 5;
    const int lane = tid & 31;
    const int mb   = w * 16;          // d tile base (4 warps cover 64 d)

    const int gtok0 = blockIdx.x * TMB;

    // staging ids: 8 threads per token row, 8 k's per chunk each
    const int row = tid >> 3;         // token row 0..15
    const int seg = tid & 7;          // k octet within chunk
    const float* hrow = hidden + (size_t)(gtok0 + row) * Hsz;

    // ldmatrix lane addressing (fragment mappings validated rounds 5-12)
    const int tId = lane >> 3, lr = lane & 7;
    const u32 xorv = (u32)(lr << 4);
    const u32 aRowB = (u32)((mb + lr + ((tId & 1) << 3)) << 7);
    const u32 aColB = (u32)((tId >> 1) << 4);
    const u32 bRowB = (u32)((lr + ((tId >> 1) << 3)) << 7);
    const u32 bColB = (u32)((tId & 1) << 4);

    // ---- W staging: async copy of pre-swizzled chunk into buffer bi ----
    auto stageW = [&](int c, int bi) {
        const char* src = g_Wp + c * 8192;
        u32 dst = sb + W_OFF + bi * 8192;
        cp_async16(dst + tid * 16,         src + tid * 16);
        cp_async16(dst + (tid + 128) * 16, src + (tid + 128) * 16);
        cp_async16(dst + (tid + 256) * 16, src + (tid + 256) * 16);
        cp_async16(dst + (tid + 384) * 16, src + (tid + 384) * 16);
        CP_COMMIT();
    };

    // kick off W chunk 0 before the (long) X prologue
    stageW(0, 0);

    // ---- prologue: convert ALL of X to fp16 smem; fuse V = h . Ws ----
    float vpart = 0.0f;
    {
        const u32 xw = ((u32)seg << 4) ^ ((u32)(row & 7) << 4);
        const u32 rb = (u32)(row << 7) + xw;
        #pragma unroll 4
        for (int c = 0; c < NCHUNK; c++) {
            const int k0 = c * KCH + seg * 8;
            float4 a0 = *(const float4*)(hrow + k0);
            float4 a1 = *(const float4*)(hrow + k0 + 4);
            float4 s0 = *(const float4*)(Ws + k0);
            float4 s1 = *(const float4*)(Ws + k0 + 4);
            vpart = fmaf(a0.x, s0.x, fmaf(a0.y, s0.y, fmaf(a0.z, s0.z, fmaf(a0.w, s0.w, vpart))));
            vpart = fmaf(a1.x, s1.x, fmaf(a1.y, s1.y, fmaf(a1.z, s1.z, fmaf(a1.w, s1.w, vpart))));
            *(uint4*)(smem + X_OFF + c * 2048 + rb) =
                make_uint4(pack_h2(a0.x, a0.y), pack_h2(a0.z, a0.w),
                           pack_h2(a1.x, a1.y), pack_h2(a1.z, a1.w));
        }
    }

    float acc[2][4];
    #pragma unroll
    for (int i = 0; i < 2; i++)
        #pragma unroll
        for (int j = 0; j < 4; j++) acc[i][j] = 0.0f;

    // ---- main loop: W double-buffered via cp.async; X static ----
    for (int c = 0; c < NCHUNK; c++) {
        const int bi = c & 1;
        CP_WAIT0();            // group c landed (issued one barrier-period ago)
        __syncthreads();       // visibility + all warps done with buffer 1-bi
        if (c + 1 < NCHUNK) stageW(c + 1, 1 - bi);   // flight covered by compute

        const u32 xh = sb + X_OFF + (u32)(c * 2048);
        const u32 wh = sb + W_OFF + (u32)(bi * 8192);
        u32 ah[4][4];
        #pragma unroll
        for (int ks = 0; ks < 4; ks++)
            ldsm4(ah[ks], wh + aRowB + (((u32)(ks << 5) + aColB) ^ xorv));
        #pragma unroll
        for (int ks = 0; ks < 4; ks++) {
            const u32 kc = (u32)(ks << 5);
            u32 b0[4];
            ldsm4(b0, xh + bRowB + ((kc + bColB) ^ xorv));
            mma_fp16(acc[0], ah[ks], b0[0], b0[1]);
            mma_fp16(acc[1], ah[ks], b0[2], b0[3]);
        }
    }

    // ---- V: 8 lanes per token row ----
    vpart += __shfl_xor_sync(0xffffffffu, vpart, 1);
    vpart += __shfl_xor_sync(0xffffffffu, vpart, 2);
    vpart += __shfl_xor_sync(0xffffffffu, vpart, 4);
    if ((tid & 7) == 0) g_V[gtok0 + row] = vpart;

    // ---- E partials: relu(acc + b1) . W2 over this warp's 16 d's ----
    {
        const int g = lane >> 2;
        const int d1 = mb + g, d2 = mb + 8 + g;
        const float b1a = b1[d1], b1b = b1[d2];
        const float w2a = W2[d1], w2b = W2[d2];
        #pragma unroll
        for (int j = 0; j < 2; j++) {
            float p0 = fmaxf(acc[j][0] + b1a, 0.0f) * w2a + fmaxf(acc[j][2] + b1b, 0.0f) * w2b;
            float p1 = fmaxf(acc[j][1] + b1a, 0.0f) * w2a + fmaxf(acc[j][3] + b1b, 0.0f) * w2b;
            p0 += __shfl_xor_sync(0xffffffffu, p0, 4);
            p0 += __shfl_xor_sync(0xffffffffu, p0, 8);
            p0 += __shfl_xor_sync(0xffffffffu, p0, 16);
            p1 += __shfl_xor_sync(0xffffffffu, p1, 4);
            p1 += __shfl_xor_sync(0xffffffffu, p1, 8);
            p1 += __shfl_xor_sync(0xffffffffu, p1, 16);
            if (lane < 4) {
                Epart[w * TMB + j * 8 + 2 * lane]     = p0;
                Epart[w * TMB + j * 8 + 2 * lane + 1] = p1;
            }
        }
    }
    __syncthreads();
    if (tid < TMB) {
        float e = Epart[0 * TMB + tid] + Epart[1 * TMB + tid]
                + Epart[2 * TMB + tid] + Epart[3 * TMB + tid];
        g_E[gtok0 + tid] = e + b2[0];
    }
}

// ---------------- Kernel 2: spans, thread per (b,s,l) ----------------
#define SPB 64   // spans per block (512 threads)
__global__ __launch_bounds__(512) void span_kernel(
    const int* __restrict__ seqlen,
    const float* __restrict__ bs,
    float* __restrict__ out)
{
    __shared__ float Es[SPB + Lsz];
    __shared__ float Vs[SPB + Lsz];

    const int tid = threadIdx.x;
    const int idx0 = blockIdx.x * SPB;
    const int b = idx0 >> 9;
    const int s0 = idx0 & (Ssz - 1);
    const int len = seqlen[b];

    if (tid < SPB + Lsz) {
        int p = min(s0 + tid, Ssz - 1);
        Es[tid] = g_E[(b << 9) + p];
        Vs[tid] = g_V[(b << 9) + p];
    }
    __syncthreads();

    const int sl = tid >> 3;          // span within block
    const int l  = tid & 7;
    const int s  = s0 + sl;
    const float bsv = bs[0];

    float M = -1e30f;
    #pragma unroll
    for (int j = 0; j < Lsz; j++)
        if (j <= l && s + j < len) M = fmaxf(M, Es[sl + j]);

    float sum = 0.0f, wsum = 0.0f;
    #pragma unroll
    for (int j = 0; j < Lsz; j++)
        if (j <= l && s + j < len) {
            float p = __expf(Es[sl + j] - M);
            sum += p;
            wsum = fmaf(p, Vs[sl + j], wsum);
        }

    float score = (sum > 0.0f) ? (wsum / sum + bsv) : bsv;
    out[(size_t)(idx0 + sl) * Lsz + l] = (s < len) ? score : 0.0f;
}

extern "C" void kernel_launch(void* const* d_in, const int* in_sizes, int n_in,
                              void* d_out, int out_size)
{
    const float* hidden = (const float*)d_in[0];
    const int*   seqlen = (const int*)  d_in[1];
    const float* tw     = (const float*)d_in[2];
    const float* W1     = (const float*)d_in[3];
    const float* b1     = (const float*)d_in[4];
    const float* W2     = (const float*)d_in[5];
    const float* b2     = (const float*)d_in[6];
    const float* Ws     = (const float*)d_in[7];
    const float* bs     = (const float*)d_in[8];
    float* out = (float*)d_out;

    static bool attr_set = false;
    if (!attr_set) {
        cudaFuncSetAttribute(token_mlp_mma,
                             cudaFuncAttributeMaxDynamicSharedMemorySize, SMEM_TOTAL);
        attr_set = true;
    }

    prep_wp<<<32, 256>>>(tw, W1);
    token_mlp_mma<<<(Bsz * Ssz) / TMB, 128, SMEM_TOTAL>>>(hidden, b1, W2, b2, Ws);
    span_kernel<<<(Bsz * Ssz) / SPB, 512>>>(seqlen, bs, out);
}

// round 14
// speedup vs baseline: 1.0661x; 1.0661x over previous
#include <cuda_runtime.h>
#include <cuda_fp16.h>
#include <cstdint>

// Problem constants
#define Bsz 32
#define Ssz 512
#define Lsz 8
#define Hsz 1024
#define Dsz 64

typedef uint32_t u32;

// Scratch
__device__ float g_E[Bsz * Ssz];
__device__ float g_V[Bsz * Ssz];
// W' = diag(tw) @ W1, fp16, [chunk][d][k] in the exact swizzled smem image (16 x 8 KB)
__device__ __align__(16) char g_Wp[16 * 8192];

// ---------------- PTX wrappers (base ISA, sm_80+) ----------------
__device__ __forceinline__ u32 smem_u32(const void* p) {
    u32 a;
    asm("{ .reg .u64 t; cvta.to.shared.u64 t, %1; cvt.u32.u64 %0, t; }" : "=r"(a) : "l"(p));
    return a;
}
__device__ __forceinline__ void ldsm4(u32* r, u32 addr) {
    asm volatile("ldmatrix.sync.aligned.m8n8.x4.shared.b16 {%0,%1,%2,%3}, [%4];"
                 : "=r"(r[0]), "=r"(r[1]), "=r"(r[2]), "=r"(r[3]) : "r"(addr));
}
__device__ __forceinline__ void mma_fp16(float* c, const u32* a, u32 b0, u32 b1) {
    asm volatile("mma.sync.aligned.m16n8k16.row.col.f32.f16.f16.f32 "
                 "{%0,%1,%2,%3}, {%4,%5,%6,%7}, {%8,%9}, {%0,%1,%2,%3};"
                 : "+f"(c[0]), "+f"(c[1]), "+f"(c[2]), "+f"(c[3])
                 : "r"(a[0]), "r"(a[1]), "r"(a[2]), "r"(a[3]), "r"(b0), "r"(b1));
}
__device__ __forceinline__ u32 pack_h2(float a, float b) {
    __half2 h = __floats2half2_rn(a, b);
    return *reinterpret_cast<u32*>(&h);
}
__device__ __forceinline__ void cp_async16(u32 dst, const void* src) {
    asm volatile("cp.async.cg.shared.global [%0], [%1], 16;" :: "r"(dst), "l"(src));
}
#define CP_COMMIT() asm volatile("cp.async.commit_group;" ::: "memory")
#define CP_WAIT2()  asm volatile("cp.async.wait_group 2;" ::: "memory")

// ---------------- Kernel 0: W' = tw * W1 -> fp16, pre-swizzled ----------------
__global__ __launch_bounds__(256) void prep_wp(
    const float* __restrict__ tw, const float* __restrict__ W1)
{
    int u = blockIdx.x * 256 + threadIdx.x;   // 0..8191
    int d = u & 63;
    int g = u >> 6;                           // k-octet 0..127
    int k0 = g * 8;
    u32 p[4];
    #pragma unroll
    for (int j = 0; j < 4; j++) {
        float wa = W1[(size_t)(k0 + 2 * j) * Dsz + d]     * tw[k0 + 2 * j];
        float wb = W1[(size_t)(k0 + 2 * j + 1) * Dsz + d] * tw[k0 + 2 * j + 1];
        p[j] = pack_h2(wa, wb);
    }
    int c = g >> 3;
    u32 seg = (u32)(g & 7);
    u32 off = (u32)(c * 8192) + (u32)(d << 7) + ((seg << 4) ^ ((u32)(d & 7) << 4));
    *(uint4*)(g_Wp + off) = make_uint4(p[0], p[1], p[2], p[3]);
}

// ---------------- Kernel 1: token MLP, X resident, warp-private W, no barriers ----------------
#define TMB 16                // tokens per block
#define KCH 64                // K per chunk
#define NCHUNK (Hsz / KCH)    // 16
#define X_OFF 0               // X: 16 chunks x 2 KB = 32 KB
#define W_OFF 32768           // W: 4 warps x 3 bufs x 2 KB = 24 KB
#define WBUF_W 6144           // per-warp region
#define EP_OFF (W_OFF + 24576)          // 57344
#define SMEM_TOTAL (EP_OFF + 4 * TMB * 4)   // 57600

__global__ __launch_bounds__(128, 3) void token_mlp_mma(
    const float* __restrict__ hidden,
    const float* __restrict__ b1,
    const float* __restrict__ W2,
    const float* __restrict__ b2,
    const float* __restrict__ Ws)
{
    extern __shared__ char smem[];
    const u32 sb = smem_u32(smem);
    float* Epart = (float*)(smem + EP_OFF);

    const int tid  = threadIdx.x;
    const int w    = tid >> 5;
    const int lane = tid & 31;
    const int mb   = w * 16;          // this warp's d tile (rows mb..mb+15 of W)

    const int gtok0 = blockIdx.x * TMB;

    // X prologue ids: 8 threads per token row, 8 k's per chunk each
    const int row = tid >> 3;
    const int seg = tid & 7;
    const float* hrow = hidden + (size_t)(gtok0 + row) * Hsz;

    // ldmatrix lane addressing (fragment mappings validated rounds 5-13)
    const int tId = lane >> 3, lr = lane & 7;
    const u32 xorv = (u32)(lr << 4);
    const u32 aRowB = (u32)((lr + ((tId & 1) << 3)) << 7);   // local rows 0..15
    const u32 aColB = (u32)((tId >> 1) << 4);
    const u32 bRowB = (u32)((lr + ((tId >> 1) << 3)) << 7);
    const u32 bColB = (u32)((tId & 1) << 4);

    const u32 wbase = sb + W_OFF + (u32)(w * WBUF_W);

    // ---- warp-private W staging: 128 x 16B units per chunk, 4 per lane ----
    auto stageW = [&](int c, int bi) {
        const char* src = g_Wp + c * 8192 + mb * 128;
        u32 dst = wbase + (u32)(bi * 2048);
        cp_async16(dst + lane * 16,          src + lane * 16);
        cp_async16(dst + (lane + 32) * 16,   src + (lane + 32) * 16);
        cp_async16(dst + (lane + 64) * 16,   src + (lane + 64) * 16);
        cp_async16(dst + (lane + 96) * 16,   src + (lane + 96) * 16);
        CP_COMMIT();
    };

    // prime 3 chunks (flight covered by the X prologue)
    stageW(0, 0);
    stageW(1, 1);
    stageW(2, 2);

    // ---- prologue: convert ALL of X to fp16 smem; fuse V = h . Ws ----
    float vpart = 0.0f;
    {
        const u32 rb = (u32)(row << 7) + ((((u32)seg << 4)) ^ ((u32)(row & 7) << 4));
        #pragma unroll 4
        for (int c = 0; c < NCHUNK; c++) {
            const int k0 = c * KCH + seg * 8;
            float4 a0 = *(const float4*)(hrow + k0);
            float4 a1 = *(const float4*)(hrow + k0 + 4);
            float4 s0 = *(const float4*)(Ws + k0);
            float4 s1 = *(const float4*)(Ws + k0 + 4);
            vpart = fmaf(a0.x, s0.x, fmaf(a0.y, s0.y, fmaf(a0.z, s0.z, fmaf(a0.w, s0.w, vpart))));
            vpart = fmaf(a1.x, s1.x, fmaf(a1.y, s1.y, fmaf(a1.z, s1.z, fmaf(a1.w, s1.w, vpart))));
            *(uint4*)(smem + X_OFF + c * 2048 + rb) =
                make_uint4(pack_h2(a0.x, a0.y), pack_h2(a0.z, a0.w),
                           pack_h2(a1.x, a1.y), pack_h2(a1.z, a1.w));
        }
    }
    // V done: 8 lanes per token row
    vpart += __shfl_xor_sync(0xffffffffu, vpart, 1);
    vpart += __shfl_xor_sync(0xffffffffu, vpart, 2);
    vpart += __shfl_xor_sync(0xffffffffu, vpart, 4);
    if ((tid & 7) == 0) g_V[gtok0 + row] = vpart;

    __syncthreads();   // X visible to all warps — the ONLY barrier before epilogue

    float acc[2][4];
    #pragma unroll
    for (int i = 0; i < 2; i++)
        #pragma unroll
        for (int j = 0; j < 4; j++) acc[i][j] = 0.0f;

    // ---- main loop: fully warp-independent ----
    for (int c = 0; c < NCHUNK; c++) {
        CP_WAIT2();                         // <=2 groups pending -> chunk c landed

        const u32 xh = sb + X_OFF + (u32)(c * 2048);
        const u32 wh = wbase + (u32)((c % 3) * 2048);
        u32 ah[4][4];
        #pragma unroll
        for (int ks = 0; ks < 4; ks++)
            ldsm4(ah[ks], wh + aRowB + (((u32)(ks << 5) + aColB) ^ xorv));
        #pragma unroll
        for (int ks = 0; ks < 4; ks++) {
            const u32 kc = (u32)(ks << 5);
            u32 b0[4];
            ldsm4(b0, xh + bRowB + ((kc + bColB) ^ xorv));
            mma_fp16(acc[0], ah[ks], b0[0], b0[1]);
            mma_fp16(acc[1], ah[ks], b0[2], b0[3]);
        }

        if (c + 3 < NCHUNK) stageW(c + 3, (c + 3) % 3);   // refill just-freed buffer
    }

    // ---- E partials: relu(acc + b1) . W2 over this warp's 16 d's ----
    {
        const int g = lane >> 2;
        const int d1 = mb + g, d2 = mb + 8 + g;
        const float b1a = b1[d1], b1b = b1[d2];
        const float w2a = W2[d1], w2b = W2[d2];
        #pragma unroll
        for (int j = 0; j < 2; j++) {
            float p0 = fmaxf(acc[j][0] + b1a, 0.0f) * w2a + fmaxf(acc[j][2] + b1b, 0.0f) * w2b;
            float p1 = fmaxf(acc[j][1] + b1a, 0.0f) * w2a + fmaxf(acc[j][3] + b1b, 0.0f) * w2b;
            p0 += __shfl_xor_sync(0xffffffffu, p0, 4);
            p0 += __shfl_xor_sync(0xffffffffu, p0, 8);
            p0 += __shfl_xor_sync(0xffffffffu, p0, 16);
            p1 += __shfl_xor_sync(0xffffffffu, p1, 4);
            p1 += __shfl_xor_sync(0xffffffffu, p1, 8);
            p1 += __shfl_xor_sync(0xffffffffu, p1, 16);
            if (lane < 4) {
                Epart[w * TMB + j * 8 + 2 * lane]     = p0;
                Epart[w * TMB + j * 8 + 2 * lane + 1] = p1;
            }
        }
    }
    __syncthreads();
    if (tid < TMB) {
        float e = Epart[0 * TMB + tid] + Epart[1 * TMB + tid]
                + Epart[2 * TMB + tid] + Epart[3 * TMB + tid];
        g_E[gtok0 + tid] = e + b2[0];
    }
}

// ---------------- Kernel 2: spans, thread per (b,s,l) ----------------
#define SPB 64   // spans per block (512 threads)
__global__ __launch_bounds__(512) void span_kernel(
    const int* __restrict__ seqlen,
    const float* __restrict__ bs,
    float* __restrict__ out)
{
    __shared__ float Es[SPB + Lsz];
    __shared__ float Vs[SPB + Lsz];

    const int tid = threadIdx.x;
    const int idx0 = blockIdx.x * SPB;
    const int b = idx0 >> 9;
    const int s0 = idx0 & (Ssz - 1);
    const int len = seqlen[b];

    if (tid < SPB + Lsz) {
        int p = min(s0 + tid, Ssz - 1);
        Es[tid] = g_E[(b << 9) + p];
        Vs[tid] = g_V[(b << 9) + p];
    }
    __syncthreads();

    const int sl = tid >> 3;          // span within block
    const int l  = tid & 7;
    const int s  = s0 + sl;
    const float bsv = bs[0];

    float M = -1e30f;
    #pragma unroll
    for (int j = 0; j < Lsz; j++)
        if (j <= l && s + j < len) M = fmaxf(M, Es[sl + j]);

    float sum = 0.0f, wsum = 0.0f;
    #pragma unroll
    for (int j = 0; j < Lsz; j++)
        if (j <= l && s + j < len) {
            float p = __expf(Es[sl + j] - M);
            sum += p;
            wsum = fmaf(p, Vs[sl + j], wsum);
        }

    float score = (sum > 0.0f) ? (wsum / sum + bsv) : bsv;
    out[(size_t)(idx0 + sl) * Lsz + l] = (s < len) ? score : 0.0f;
}

extern "C" void kernel_launch(void* const* d_in, const int* in_sizes, int n_in,
                              void* d_out, int out_size)
{
    const float* hidden = (const float*)d_in[0];
    const int*   seqlen = (const int*)  d_in[1];
    const float* tw     = (const float*)d_in[2];
    const float* W1     = (const float*)d_in[3];
    const float* b1     = (const float*)d_in[4];
    const float* W2     = (const float*)d_in[5];
    const float* b2     = (const float*)d_in[6];
    const float* Ws     = (const float*)d_in[7];
    const float* bs     = (const float*)d_in[8];
    float* out = (float*)d_out;

    static bool attr_set = false;
    if (!attr_set) {
        cudaFuncSetAttribute(token_mlp_mma,
                             cudaFuncAttributeMaxDynamicSharedMemorySize, SMEM_TOTAL);
        attr_set = true;
    }

    prep_wp<<<32, 256>>>(tw, W1);
    token_mlp_mma<<<(Bsz * Ssz) / TMB, 128, SMEM_TOTAL>>>(hidden, b1, W2, b2, Ws);
    span_kernel<<<(Bsz * Ssz) / SPB, 512>>>(seqlen, bs, out);
}

// round 15
// speedup vs baseline: 1.1491x; 1.0779x over previous
#include <cuda_runtime.h>
#include <cuda_fp16.h>
#include <cstdint>

// Problem constants
#define Bsz 32
#define Ssz 512
#define Lsz 8
#define Hsz 1024
#define Dsz 64

typedef uint32_t u32;

// Scratch
__device__ float g_E[Bsz * Ssz];
__device__ float g_V[Bsz * Ssz];
// W' = diag(tw) @ W1, fp16, [chunk][d][k] in the exact swizzled smem image (16 x 8 KB)
__device__ __align__(16) char g_Wp[16 * 8192];

// ---------------- PTX wrappers (base ISA, sm_80+) ----------------
__device__ __forceinline__ u32 smem_u32(const void* p) {
    u32 a;
    asm("{ .reg .u64 t; cvta.to.shared.u64 t, %1; cvt.u32.u64 %0, t; }" : "=r"(a) : "l"(p));
    return a;
}
__device__ __forceinline__ void ldsm4(u32* r, u32 addr) {
    asm volatile("ldmatrix.sync.aligned.m8n8.x4.shared.b16 {%0,%1,%2,%3}, [%4];"
                 : "=r"(r[0]), "=r"(r[1]), "=r"(r[2]), "=r"(r[3]) : "r"(addr));
}
__device__ __forceinline__ void mma_fp16(float* c, const u32* a, u32 b0, u32 b1) {
    asm volatile("mma.sync.aligned.m16n8k16.row.col.f32.f16.f16.f32 "
                 "{%0,%1,%2,%3}, {%4,%5,%6,%7}, {%8,%9}, {%0,%1,%2,%3};"
                 : "+f"(c[0]), "+f"(c[1]), "+f"(c[2]), "+f"(c[3])
                 : "r"(a[0]), "r"(a[1]), "r"(a[2]), "r"(a[3]), "r"(b0), "r"(b1));
}
__device__ __forceinline__ u32 pack_h2(float a, float b) {
    __half2 h = __floats2half2_rn(a, b);
    return *reinterpret_cast<u32*>(&h);
}
__device__ __forceinline__ void cp_async16(u32 dst, const void* src) {
    asm volatile("cp.async.cg.shared.global [%0], [%1], 16;" :: "r"(dst), "l"(src));
}
#define CP_COMMIT() asm volatile("cp.async.commit_group;" ::: "memory")
#define CP_WAIT0()  asm volatile("cp.async.wait_group 0;" ::: "memory")

// ---------------- Kernel 0: W' = tw * W1 -> fp16, pre-swizzled ----------------
// Max parallelism: 32768 threads, each 2 coalesced LDG.32 + 1 STG.32, no smem/barrier.
__global__ __launch_bounds__(256) void prep_wp(
    const float* __restrict__ tw, const float* __restrict__ W1)
{
    int u = blockIdx.x * 256 + threadIdx.x;   // 0..32767
    int d = u & 63;
    int p = u >> 6;                           // k-pair 0..511
    int k0 = p * 2;
    float wa = W1[(size_t)k0 * Dsz + d]       * tw[k0];
    float wb = W1[(size_t)(k0 + 1) * Dsz + d] * tw[k0 + 1];
    u32 v = pack_h2(wa, wb);
    int g = p >> 2;            // k-octet
    int q = p & 3;             // pair within octet
    int c = g >> 3;
    u32 seg = (u32)(g & 7);
    u32 off = (u32)(c * 8192) + (u32)(d << 7)
            + ((seg << 4) ^ ((u32)(d & 7) << 4)) + (u32)(q * 4);
    *(u32*)(g_Wp + off) = v;
}

// ---------------- Kernel 1: token MLP via fp16 mma.sync (round-12 structure) ----------------
#define TMB 16                // tokens per block
#define KCH 64                // K per chunk
#define NCHUNK (Hsz / KCH)    // 16
#define XH_OFF 0              // X: 16 rows x 128B = 2KB
#define WH_OFF 2048           // W: 64 rows x 128B = 8KB
#define BUFS   10240
#define EP_OFF (2 * BUFS)                 // 20480
#define WS_OFF (EP_OFF + 4 * TMB * 4)     // 20736
#define SMEM_TOTAL (WS_OFF + Hsz * 4)     // 24832

__global__ __launch_bounds__(128, 6) void token_mlp_mma(
    const float* __restrict__ hidden,
    const float* __restrict__ b1,
    const float* __restrict__ W2,
    const float* __restrict__ b2,
    const float* __restrict__ Ws)
{
    extern __shared__ char smem[];
    const u32 sb = smem_u32(smem);
    float* Epart = (float*)(smem + EP_OFF);
    float* WsS   = (float*)(smem + WS_OFF);

    const int tid  = threadIdx.x;
    const int w    = tid >> 5;
    const int lane = tid & 31;
    const int mb   = w * 16;          // d tile base (4 warps cover 64 d)

    const int gtok0 = blockIdx.x * TMB;

    // X staging ids: 8 threads per token row, 8 k's each
    const int row = tid >> 3;         // token row 0..15
    const int seg = tid & 7;          // k octet within chunk
    const float* hrow = hidden + (size_t)(gtok0 + row) * Hsz;

    // preload Ws into smem (1024 floats / 128 threads = 8 each)
    *(float4*)(WsS + tid * 8)     = *(const float4*)(Ws + tid * 8);
    *(float4*)(WsS + tid * 8 + 4) = *(const float4*)(Ws + tid * 8 + 4);

    // ldmatrix lane addressing (fragment mappings validated rounds 5-12)
    const int tId = lane >> 3, lr = lane & 7;
    const u32 xorv = (u32)(lr << 4);
    const u32 aRowB = (u32)((mb + lr + ((tId & 1) << 3)) << 7);
    const u32 aColB = (u32)((tId >> 1) << 4);
    const u32 bRowB = (u32)((lr + ((tId >> 1) << 3)) << 7);
    const u32 bColB = (u32)((tId & 1) << 4);

    float acc[2][4];
    #pragma unroll
    for (int i = 0; i < 2; i++)
        #pragma unroll
        for (int j = 0; j < 4; j++) acc[i][j] = 0.0f;
    float vpart = 0.0f;

    __syncthreads();   // WsS ready

    // ---------- staging: chunk c into buffer bi ----------
    auto stage = [&](int c, int bi) {
        char* bp = smem + bi * BUFS;
        const int k0 = c * KCH + seg * 8;
        // X: x = fp16(h); fuse V = h . Ws
        {
            float4 a0 = *(const float4*)(hrow + k0);
            float4 a1 = *(const float4*)(hrow + k0 + 4);
            float4 s0 = *(const float4*)(WsS + k0);
            float4 s1 = *(const float4*)(WsS + k0 + 4);
            vpart = fmaf(a0.x, s0.x, fmaf(a0.y, s0.y, fmaf(a0.z, s0.z, fmaf(a0.w, s0.w, vpart))));
            vpart = fmaf(a1.x, s1.x, fmaf(a1.y, s1.y, fmaf(a1.z, s1.z, fmaf(a1.w, s1.w, vpart))));
            u32 off = (u32)(row << 7) + (((u32)seg << 4) ^ ((u32)(row & 7) << 4));
            *(uint4*)(bp + XH_OFF + off) =
                make_uint4(pack_h2(a0.x, a0.y), pack_h2(a0.z, a0.w),
                           pack_h2(a1.x, a1.y), pack_h2(a1.z, a1.w));
        }
        // W: async copy of pre-swizzled chunk (512 x 16B units / 128 threads = 4 each)
        {
            const char* src = g_Wp + c * 8192;
            u32 dst = sb + bi * BUFS + WH_OFF;
            cp_async16(dst + tid * 16,         src + tid * 16);
            cp_async16(dst + (tid + 128) * 16, src + (tid + 128) * 16);
            cp_async16(dst + (tid + 256) * 16, src + (tid + 256) * 16);
            cp_async16(dst + (tid + 384) * 16, src + (tid + 384) * 16);
            CP_COMMIT();
        }
    };

    // ---------- compute one chunk from buffer bi ----------
    auto compute = [&](int bi) {
        const u32 xh = sb + bi * BUFS + XH_OFF;
        const u32 wh = sb + bi * BUFS + WH_OFF;
        u32 ah[4][4];
        #pragma unroll
        for (int ks = 0; ks < 4; ks++)
            ldsm4(ah[ks], wh + aRowB + (((u32)(ks << 5) + aColB) ^ xorv));
        #pragma unroll
        for (int ks = 0; ks < 4; ks++) {
            const u32 kc = (u32)(ks << 5);
            u32 b0[4];
            ldsm4(b0, xh + bRowB + ((kc + bColB) ^ xorv));
            mma_fp16(acc[0], ah[ks], b0[0], b0[1]);
            mma_fp16(acc[1], ah[ks], b0[2], b0[3]);
        }
    };

    stage(0, 0);
    CP_WAIT0();
    __syncthreads();

    for (int c = 0; c < NCHUNK; c++) {
        const int bi = c & 1;
        if (c + 1 < NCHUNK) stage(c + 1, 1 - bi);
        compute(bi);
        CP_WAIT0();
        __syncthreads();
    }

    // ---- V: 8 lanes per token row ----
    vpart += __shfl_xor_sync(0xffffffffu, vpart, 1);
    vpart += __shfl_xor_sync(0xffffffffu, vpart, 2);
    vpart += __shfl_xor_sync(0xffffffffu, vpart, 4);
    if ((tid & 7) == 0) g_V[gtok0 + row] = vpart;

    // ---- E partials: relu(acc + b1) . W2 over this warp's 16 d's ----
    {
        const int g = lane >> 2;
        const int d1 = mb + g, d2 = mb + 8 + g;
        const float b1a = b1[d1], b1b = b1[d2];
        const float w2a = W2[d1], w2b = W2[d2];
        #pragma unroll
        for (int j = 0; j < 2; j++) {
            float p0 = fmaxf(acc[j][0] + b1a, 0.0f) * w2a + fmaxf(acc[j][2] + b1b, 0.0f) * w2b;
            float p1 = fmaxf(acc[j][1] + b1a, 0.0f) * w2a + fmaxf(acc[j][3] + b1b, 0.0f) * w2b;
            p0 += __shfl_xor_sync(0xffffffffu, p0, 4);
            p0 += __shfl_xor_sync(0xffffffffu, p0, 8);
            p0 += __shfl_xor_sync(0xffffffffu, p0, 16);
            p1 += __shfl_xor_sync(0xffffffffu, p1, 4);
            p1 += __shfl_xor_sync(0xffffffffu, p1, 8);
            p1 += __shfl_xor_sync(0xffffffffu, p1, 16);
            if (lane < 4) {
                Epart[w * TMB + j * 8 + 2 * lane]     = p0;
                Epart[w * TMB + j * 8 + 2 * lane + 1] = p1;
            }
        }
    }
    __syncthreads();
    if (tid < TMB) {
        float e = Epart[0 * TMB + tid] + Epart[1 * TMB + tid]
                + Epart[2 * TMB + tid] + Epart[3 * TMB + tid];
        g_E[gtok0 + tid] = e + b2[0];
    }
}

// ---------------- Kernel 2: spans, thread per (b,s,l) ----------------
#define SPB 64   // spans per block (512 threads)
__global__ __launch_bounds__(512) void span_kernel(
    const int* __restrict__ seqlen,
    const float* __restrict__ bs,
    float* __restrict__ out)
{
    __shared__ float Es[SPB + Lsz];
    __shared__ float Vs[SPB + Lsz];

    const int tid = threadIdx.x;
    const int idx0 = blockIdx.x * SPB;
    const int b = idx0 >> 9;
    const int s0 = idx0 & (Ssz - 1);
    const int len = seqlen[b];

    if (tid < SPB + Lsz) {
        int p = min(s0 + tid, Ssz - 1);
        Es[tid] = g_E[(b << 9) + p];
        Vs[tid] = g_V[(b << 9) + p];
    }
    __syncthreads();

    const int sl = tid >> 3;          // span within block
    const int l  = tid & 7;
    const int s  = s0 + sl;
    const float bsv = bs[0];

    float M = -1e30f;
    #pragma unroll
    for (int j = 0; j < Lsz; j++)
        if (j <= l && s + j < len) M = fmaxf(M, Es[sl + j]);

    float sum = 0.0f, wsum = 0.0f;
    #pragma unroll
    for (int j = 0; j < Lsz; j++)
        if (j <= l && s + j < len) {
            float p = __expf(Es[sl + j] - M);
            sum += p;
            wsum = fmaf(p, Vs[sl + j], wsum);
        }

    float score = (sum > 0.0f) ? (wsum / sum + bsv) : bsv;
    out[(size_t)(idx0 + sl) * Lsz + l] = (s < len) ? score : 0.0f;
}

extern "C" void kernel_launch(void* const* d_in, const int* in_sizes, int n_in,
                              void* d_out, int out_size)
{
    const float* hidden = (const float*)d_in[0];
    const int*   seqlen = (const int*)  d_in[1];
    const float* tw     = (const float*)d_in[2];
    const float* W1     = (const float*)d_in[3];
    const float* b1     = (const float*)d_in[4];
    const float* W2     = (const float*)d_in[5];
    const float* b2     = (const float*)d_in[6];
    const float* Ws     = (const float*)d_in[7];
    const float* bs     = (const float*)d_in[8];
    float* out = (float*)d_out;

    static bool attr_set = false;
    if (!attr_set) {
        cudaFuncSetAttribute(token_mlp_mma,
                             cudaFuncAttributeMaxDynamicSharedMemorySize, SMEM_TOTAL);
        attr_set = true;
    }

    prep_wp<<<128, 256>>>(tw, W1);
    token_mlp_mma<<<(Bsz * Ssz) / TMB, 128, SMEM_TOTAL>>>(hidden, b1, W2, b2, Ws);
    span_kernel<<<(Bsz * Ssz) / SPB, 512>>>(seqlen, bs, out);
}